// round 16
// baseline (speedup 1.0000x reference)
#include <cuda_runtime.h>
#include <cuda_bf16.h>
#include <cstdint>
#include <math.h>

#define LQ   2048
#define CD   2048
#define HN   16
#define DD   128
#define KVL  4096
#define LC_  ((size_t)LQ * CD)

// ---------------- scratch (device globals; no allocation) ----------------
__device__ __nv_bfloat16 gQh [LQ  * CD];    // normed+roped+scaled Q, bf16
__device__ __nv_bfloat16 gKh [KVL * CD];    // normed+roped K, bf16
__device__ __nv_bfloat16 gVTh[CD  * KVL];   // V transposed, bf16: [c][kv]
__device__ __nv_bfloat16 gBF [6 * LQ * CD]; // bf16: h0,h1,h2,Wq,Wk,Wv
__device__ float gAO[LQ  * CD];
__device__ float gO [LQ  * CD];
__device__ float gPH[LQ  * CD];
__device__ float gPS[LQ  * CD];
__device__ float gRC[3 * 64];
__device__ float gRS[3 * 64];

// ---------------- helpers ----------------
__device__ __forceinline__ uint32_t packbf(float lo, float hi) {
    __nv_bfloat162 h = __floats2bfloat162_rn(lo, hi);
    return *(uint32_t*)&h;
}
__device__ __forceinline__ void mma_tf32(float c[4], const uint32_t a[4], const uint32_t b[2]) {
    asm volatile(
        "mma.sync.aligned.m16n8k8.row.col.f32.tf32.tf32.f32 "
        "{%0,%1,%2,%3}, {%4,%5,%6,%7}, {%8,%9}, {%0,%1,%2,%3};"
        : "+f"(c[0]), "+f"(c[1]), "+f"(c[2]), "+f"(c[3])
        : "r"(a[0]), "r"(a[1]), "r"(a[2]), "r"(a[3]), "r"(b[0]), "r"(b[1]));
}
__device__ __forceinline__ void mma_bf16(float c[4], const uint32_t a[4], const uint32_t b[2]) {
    asm volatile(
        "mma.sync.aligned.m16n8k16.row.col.f32.bf16.bf16.f32 "
        "{%0,%1,%2,%3}, {%4,%5,%6,%7}, {%8,%9}, {%0,%1,%2,%3};"
        : "+f"(c[0]), "+f"(c[1]), "+f"(c[2]), "+f"(c[3])
        : "r"(a[0]), "r"(a[1]), "r"(a[2]), "r"(a[3]), "r"(b[0]), "r"(b[1]));
}
__device__ __forceinline__ void ldsm4(uint32_t* r, uint32_t addr) {
    asm volatile("ldmatrix.sync.aligned.m8n8.x4.shared.b16 {%0,%1,%2,%3}, [%4];"
        : "=r"(r[0]), "=r"(r[1]), "=r"(r[2]), "=r"(r[3]) : "r"(addr));
}

#define CPASYNC16(dst, src) \
    asm volatile("cp.async.cg.shared.global [%0], [%1], 16;" :: "r"(dst), "l"(src) : "memory")
#define CPCOMMIT()   asm volatile("cp.async.commit_group;" ::: "memory")
#define CPWAIT1()    asm volatile("cp.async.wait_group 1;" ::: "memory")
#define CPWAIT0()    asm volatile("cp.async.wait_group 0;" ::: "memory")

// ---------------- fp32->bf16 conversion (6 tensors) ----------------
struct Cvt6 { const float* s[6]; };
__global__ __launch_bounds__(256) void convert6(Cvt6 js, __nv_bfloat16* dst)
{
    const int z = blockIdx.y;
    const size_t idx = (size_t)blockIdx.x * 256 + threadIdx.x;
    const float4 v = ((const float4*)js.s[z])[idx];
    uint2 u;
    u.x = packbf(v.x, v.y);
    u.y = packbf(v.z, v.w);
    *(uint2*)(dst + z * LC_ + idx * 4) = u;
}

// ---------------- rope tables ----------------
__global__ void ropetab()
{
    const int t = threadIdx.x;
    if (t < 192) {
        const int z = t >> 6, d = t & 63;
        const float depth = (z == 0) ? 2.f : (float)(z - 1);
        const float ang = depth * __expf(-(float)d * 0.14391156f);
        gRC[t] = cosf(ang);
        gRS[t] = sinf(ang);
    }
}

// ---------------- bf16 GEMM mainloop (projections), 3-stage ring ----------------
#define BH_S    72
#define BG_TILE (128 * BH_S * 2)            // 18432 B
#define BGSMEM  (6 * BG_TILE)               // 110592 B (epilogue tile 128x132 f32 = 67584 B fits)
#define EPS_    132                          // epilogue smem stride (floats, mult of 4 for LDS.128)

__device__ __forceinline__ void bgemm_main(
    const __nv_bfloat16* __restrict__ A, const __nv_bfloat16* __restrict__ B,
    float c[4][8][4])
{
    extern __shared__ char smc[];
    const uint32_t sbase = (uint32_t)__cvta_generic_to_shared(smc);

    const int tid  = threadIdx.x;
    const int wid  = tid >> 5, lane = tid & 31;
    const int wm   = (wid & 1) * 64;
    const int wn   = (wid >> 1) * 64;
    const int bm   = blockIdx.y * 128, bn = blockIdx.x * 128;

    const int arow  = lane & 15;
    const int acol8 = (lane >> 4) * 8;
    const int brow  = (lane & 7) + ((lane >> 4) << 3);
    const int bcol8 = ((lane >> 3) & 1) * 8;

    const int NK = CD / 64;   // 32

    auto prefetch = [&](int kc) {
        const int s = kc % 3;
        const int k0 = kc << 6;
        const uint32_t ab = sbase + (2 * s) * BG_TILE;
        const uint32_t bb = sbase + (2 * s + 1) * BG_TILE;
#pragma unroll
        for (int i = 0; i < 8; i++) {
            const int idx = i * 128 + tid;
            const int r = idx >> 3, c8 = (idx & 7) * 8;
            CPASYNC16(ab + (r * BH_S + c8) * 2, A + (size_t)(bm + r) * CD + k0 + c8);
            CPASYNC16(bb + (r * BH_S + c8) * 2, B + (size_t)(bn + r) * CD + k0 + c8);
        }
        CPCOMMIT();
    };

    prefetch(0);
    prefetch(1);

    for (int kc = 0; kc < NK; kc++) {
        if (kc + 1 < NK) CPWAIT1(); else CPWAIT0();
        __syncthreads();
        if (kc + 2 < NK) prefetch(kc + 2);

        const int s = kc % 3;
        const uint32_t Au = sbase + (2 * s) * BG_TILE;
        const uint32_t Bu = sbase + (2 * s + 1) * BG_TILE;

#pragma unroll
        for (int ks = 0; ks < 4; ks++) {
            const int k = ks * 16;
            uint32_t af[4][4], bf[8][2];
#pragma unroll
            for (int mi = 0; mi < 4; mi++)
                ldsm4(af[mi], Au + ((wm + mi * 16 + arow) * BH_S + k + acol8) * 2);
#pragma unroll
            for (int p = 0; p < 4; p++) {
                uint32_t t[4];
                ldsm4(t, Bu + ((wn + p * 16 + brow) * BH_S + k + bcol8) * 2);
                bf[2 * p][0] = t[0]; bf[2 * p][1] = t[1];
                bf[2 * p + 1][0] = t[2]; bf[2 * p + 1][1] = t[3];
            }
#pragma unroll
            for (int mi = 0; mi < 4; mi++)
#pragma unroll
                for (int ni = 0; ni < 8; ni++)
                    mma_bf16(c[mi][ni], af[mi], bf[ni]);
        }
    }
}

// fused projections:
//   z=0: h2*Wq  -> rmsnorm(qn)+rope(tbl0)+scale -> Qh bf16
//   z=1: h0*Wk  -> rmsnorm(kn)+rope(tbl1)       -> Kh[0]
//   z=2: h1*Wk  -> rmsnorm(kn)+rope(tbl2)       -> Kh[1]
//   z=3: h0*Wv  -> transpose                    -> VT[:, 0:2048]
//   z=4: h1*Wv  -> transpose                    -> VT[:, 2048:4096]
__global__ __launch_bounds__(128) void proj5b(
    const __nv_bfloat16* __restrict__ BF,
    __nv_bfloat16* __restrict__ Qh, __nv_bfloat16* __restrict__ Kh,
    __nv_bfloat16* __restrict__ VT,
    const float* __restrict__ qn, const float* __restrict__ kn)
{
    const int z = blockIdx.z;
    const __nv_bfloat16 *Ap, *Bp;
    switch (z) {
        case 0:  Ap = BF + 2 * LC_; Bp = BF + 3 * LC_; break;
        case 1:  Ap = BF + 0 * LC_; Bp = BF + 4 * LC_; break;
        case 2:  Ap = BF + 1 * LC_; Bp = BF + 4 * LC_; break;
        case 3:  Ap = BF + 0 * LC_; Bp = BF + 5 * LC_; break;
        default: Ap = BF + 1 * LC_; Bp = BF + 5 * LC_; break;
    }

    float c[4][8][4];
#pragma unroll
    for (int i = 0; i < 4; i++)
#pragma unroll
        for (int j = 0; j < 8; j++)
#pragma unroll
            for (int r = 0; r < 4; r++) c[i][j][r] = 0.f;

    bgemm_main(Ap, Bp, c);

    // ---- stage accumulators to smem fp32 tile [128][EPS_] ----
    extern __shared__ char smc[];
    float* st = (float*)smc;
    const int tid  = threadIdx.x;
    const int wid  = tid >> 5, lane = tid & 31;
    const int gid  = lane >> 2, tig = lane & 3;
    const int wm   = (wid & 1) * 64;
    const int wn   = (wid >> 1) * 64;
    const int bm   = blockIdx.y * 128, bn = blockIdx.x * 128;

    __syncthreads();   // mainloop smem reads done everywhere
#pragma unroll
    for (int mi = 0; mi < 4; mi++) {
        const int r0 = wm + mi * 16 + gid;
#pragma unroll
        for (int ni = 0; ni < 8; ni++) {
            const int col = wn + ni * 8 + tig * 2;
            st[r0 * EPS_ + col]           = c[mi][ni][0];
            st[r0 * EPS_ + col + 1]       = c[mi][ni][1];
            st[(r0 + 8) * EPS_ + col]     = c[mi][ni][2];
            st[(r0 + 8) * EPS_ + col + 1] = c[mi][ni][3];
        }
    }
    __syncthreads();

    if (z <= 2) {
        // ---- rmsnorm + rope per row (warp handles 32 rows) ----
        const float* w = (z == 0) ? qn : kn;
        const float4 wv = *(const float4*)(w + lane * 4);
        const int dd0 = (lane & 15) * 4;
        const float4 cv = *(const float4*)(gRC + z * 64 + dd0);
        const float4 sv = *(const float4*)(gRS + z * 64 + dd0);
        const float qs = (z == 0) ? 0.08838834764831845f : 1.f;
        __nv_bfloat16* dst = (z == 0) ? Qh : (Kh + (size_t)(z - 1) * LC_);

        for (int r8 = 0; r8 < 32; r8++) {
            const int row = wid * 32 + r8;
            float4 v = *(const float4*)&st[row * EPS_ + lane * 4];
            float sq = v.x * v.x + v.y * v.y + v.z * v.z + v.w * v.w;
#pragma unroll
            for (int o = 16; o > 0; o >>= 1) sq += __shfl_xor_sync(0xffffffffu, sq, o);
            const float rn = rsqrtf(sq * (1.f / 128.f) + 1e-6f);

            float4 s = make_float4(v.x * rn * wv.x, v.y * rn * wv.y,
                                   v.z * rn * wv.z, v.w * rn * wv.w);
            float4 q;
            q.x = __shfl_xor_sync(0xffffffffu, s.x, 16);
            q.y = __shfl_xor_sync(0xffffffffu, s.y, 16);
            q.z = __shfl_xor_sync(0xffffffffu, s.z, 16);
            q.w = __shfl_xor_sync(0xffffffffu, s.w, 16);

            float4 out;
            if (lane < 16) {
                out.x = s.x * cv.x - q.x * sv.x;
                out.y = s.y * cv.y - q.y * sv.y;
                out.z = s.z * cv.z - q.z * sv.z;
                out.w = s.w * cv.w - q.w * sv.w;
            } else {
                out.x = q.x * sv.x + s.x * cv.x;
                out.y = q.y * sv.y + s.y * cv.y;
                out.z = q.z * sv.z + s.z * cv.z;
                out.w = q.w * sv.w + s.w * cv.w;
            }
            out.x *= qs; out.y *= qs; out.z *= qs; out.w *= qs;

            uint2 u;
            u.x = packbf(out.x, out.y);
            u.y = packbf(out.z, out.w);
            *(uint2*)(dst + (size_t)(bm + row) * CD + bn + lane * 4) = u;
        }
    } else {
        // ---- transpose to VT[c][kv] bf16 (kv = this CTA's 128 rows) ----
        const int kvb = (z == 3 ? 0 : 2048) + bm;
        for (int j = 0; j < 32; j++) {
            const int ccol = wid + 4 * j;   // 0..127
            const float a0 = st[(lane * 4 + 0) * EPS_ + ccol];
            const float a1 = st[(lane * 4 + 1) * EPS_ + ccol];
            const float a2 = st[(lane * 4 + 2) * EPS_ + ccol];
            const float a3 = st[(lane * 4 + 3) * EPS_ + ccol];
            uint2 u;
            u.x = packbf(a0, a1);
            u.y = packbf(a2, a3);
            *(uint2*)(VT + (size_t)(bn + ccol) * KVL + kvb + lane * 4) = u;
        }
    }
}

// ---------------- tf32 mma.sync GEMM core (Wo + pos), 3-stage ring ----------------
#define GS_TILE 4608
#define GSMEM   (6 * GS_TILE * 4)

template<bool BT, bool BIAS>
__device__ __forceinline__ void gemm_core(
    const float* __restrict__ A, const float* __restrict__ B,
    const float* __restrict__ bias, float* __restrict__ Cc,
    int M, int N, int K)
{
    extern __shared__ float smemf[];
    const uint32_t sbase = (uint32_t)__cvta_generic_to_shared(smemf);

    const int tid  = threadIdx.x;
    const int wid  = tid >> 5, lane = tid & 31;
    const int gid  = lane >> 2, tig = lane & 3;
    const int wm   = (wid & 1) * 64;
    const int wn   = (wid >> 1) * 64;
    const int bm   = blockIdx.y * 128, bn = blockIdx.x * 128;

    const int arow = lane & 15,                 acol = (lane >> 4) * 4;
    const int brow = (lane & 7) + ((lane >> 4) << 3), bcol = ((lane >> 3) & 1) * 4;

    float c[4][8][4];
#pragma unroll
    for (int i = 0; i < 4; i++)
#pragma unroll
        for (int j = 0; j < 8; j++)
#pragma unroll
            for (int r = 0; r < 4; r++) c[i][j][r] = 0.f;

    const int NK = K >> 5;

    auto prefetch = [&](int kc) {
        const int s = kc % 3;
        const int k0 = kc << 5;
        const uint32_t ab = sbase + ((2 * s) * GS_TILE) * 4;
        const uint32_t bb = sbase + ((2 * s + 1) * GS_TILE) * 4;
#pragma unroll
        for (int i = 0; i < 8; i++) {
            const int idx = i * 128 + tid;
            const int r = idx >> 3, cc = (idx & 7) * 4;
            CPASYNC16(ab + (r * 36 + cc) * 4, A + (size_t)(bm + r) * K + k0 + cc);
        }
        if (BT) {
#pragma unroll
            for (int i = 0; i < 8; i++) {
                const int idx = i * 128 + tid;
                const int r = idx >> 3, cc = (idx & 7) * 4;
                CPASYNC16(bb + (r * 36 + cc) * 4, B + (size_t)(bn + r) * K + k0 + cc);
            }
        } else {
#pragma unroll
            for (int i = 0; i < 8; i++) {
                const int idx = i * 128 + tid;
                const int kr = idx >> 5, cc = (idx & 31) * 4;
                CPASYNC16(bb + (kr * 132 + cc) * 4, B + (size_t)(k0 + kr) * N + bn + cc);
            }
        }
        CPCOMMIT();
    };

    prefetch(0);
    prefetch(1);

    for (int kc = 0; kc < NK; kc++) {
        if (kc + 1 < NK) CPWAIT1(); else CPWAIT0();
        __syncthreads();
        if (kc + 2 < NK) prefetch(kc + 2);

        const int s = kc % 3;
        const uint32_t sAu = sbase + ((2 * s) * GS_TILE) * 4;
        const uint32_t sBu = sbase + ((2 * s + 1) * GS_TILE) * 4;
        const float*   sB  = smemf + (2 * s + 1) * GS_TILE;

#pragma unroll
        for (int ks = 0; ks < 4; ks++) {
            const int k = ks * 8;
            uint32_t af[4][4], bf[8][2];
#pragma unroll
            for (int mi = 0; mi < 4; mi++)
                ldsm4(af[mi], sAu + (((wm + mi * 16 + arow) * 36) + k + acol) * 4);
            if (BT) {
#pragma unroll
                for (int p = 0; p < 4; p++) {
                    uint32_t t[4];
                    ldsm4(t, sBu + (((wn + p * 16 + brow) * 36) + k + bcol) * 4);
                    bf[2 * p][0] = t[0]; bf[2 * p][1] = t[1];
                    bf[2 * p + 1][0] = t[2]; bf[2 * p + 1][1] = t[3];
                }
            } else {
#pragma unroll
                for (int ni = 0; ni < 8; ni++) {
                    const int n = wn + ni * 8 + gid;
                    bf[ni][0] = __float_as_uint(sB[(k + tig    ) * 132 + n]);
                    bf[ni][1] = __float_as_uint(sB[(k + tig + 4) * 132 + n]);
                }
            }
#pragma unroll
            for (int mi = 0; mi < 4; mi++)
#pragma unroll
                for (int ni = 0; ni < 8; ni++)
                    mma_tf32(c[mi][ni], af[mi], bf[ni]);
        }
    }

#pragma unroll
    for (int mi = 0; mi < 4; mi++) {
        const int row0 = bm + wm + mi * 16 + gid;
#pragma unroll
        for (int ni = 0; ni < 8; ni++) {
            const int col = bn + wn + ni * 8 + tig * 2;
            float2 v0 = make_float2(c[mi][ni][0], c[mi][ni][1]);
            float2 v1 = make_float2(c[mi][ni][2], c[mi][ni][3]);
            if (BIAS) {
                const float b0 = bias[col], b1 = bias[col + 1];
                v0.x += b0; v0.y += b1; v1.x += b0; v1.y += b1;
            }
            *(float2*)(Cc + (size_t)row0 * N + col)       = v0;
            *(float2*)(Cc + (size_t)(row0 + 8) * N + col) = v1;
        }
    }
}

__global__ __launch_bounds__(128) void gemm2_kernel(
    const float* AO, const float* Wo, float* O,
    const float* PH, const float* sw2, const float* sb2, float* PS)
{
    if (blockIdx.z == 0)
        gemm_core<true,  false>(AO, Wo, nullptr, O, 2048, 2048, 2048);
    else
        gemm_core<false, true >(PH, sw2, sb2, PS, 2048, 2048, 2048);
}

// ---------------- flash attention: bf16 mma.sync + ldmatrix, 3-stage ring ----------------
#define KHS 136
#define TTS 72
#define PTS 72
#define KSTG (64 * KHS)
#define TSTG (128 * TTS)
#define OFF_T (3 * KSTG)
#define OFF_P (OFF_T + 3 * TSTG)
#define FSMEM ((OFF_P + 128 * PTS) * 2)

__global__ __launch_bounds__(256) void flashmma(
    const __nv_bfloat16* __restrict__ Qh, const __nv_bfloat16* __restrict__ Kh,
    const __nv_bfloat16* __restrict__ VTh, float* __restrict__ Og)
{
    extern __shared__ char smc[];
    const uint32_t smu = (uint32_t)__cvta_generic_to_shared(smc);
    const uint32_t Ktu[3] = { smu, smu + KSTG * 2, smu + 2 * KSTG * 2 };
    const uint32_t Ttu[3] = { smu + OFF_T * 2, smu + (OFF_T + TSTG) * 2,
                              smu + (OFF_T + 2 * TSTG) * 2 };
    const uint32_t Psu = smu + OFF_P * 2;
    uint32_t* Pw = (uint32_t*)(smc + OFF_P * 2);

    const int tid  = threadIdx.x;
    const int wid  = tid >> 5, lane = tid & 31;
    const int gid  = lane >> 2, tig = lane & 3;
    const int h    = blockIdx.y;
    const int q0   = blockIdx.x * 128;
    const int hD   = h * DD;
    const int w16  = wid * 16;

    const int arow = lane & 15;
    const int acol8 = (lane >> 4) * 8;
    const int brow = (lane & 7) + ((lane >> 4) << 3);
    const int bcol8 = ((lane >> 3) & 1) * 8;

    // ---- Q fragments: direct bf16 pair loads (scale pre-folded upstream) ----
    uint32_t qf[8][4];
    {
        const __nv_bfloat16* qr0 = Qh + (size_t)(q0 + w16 + gid) * CD + hD;
        const __nv_bfloat16* qr1 = qr0 + (size_t)8 * CD;
#pragma unroll
        for (int ks = 0; ks < 8; ks++) {
            const int k = ks * 16;
            qf[ks][0] = *(const uint32_t*)(qr0 + k + 2 * tig);
            qf[ks][1] = *(const uint32_t*)(qr1 + k + 2 * tig);
            qf[ks][2] = *(const uint32_t*)(qr0 + k + 2 * tig + 8);
            qf[ks][3] = *(const uint32_t*)(qr1 + k + 2 * tig + 8);
        }
    }

    auto prefetch = [&](int it) {
        const int s = it % 3;
        const int k0 = it * 64;
        const uint32_t kd = Ktu[s];
        const uint32_t td = Ttu[s];
#pragma unroll
        for (int i = 0; i < 4; i++) {
            const int idx = i * 256 + tid;
            const int r = idx >> 4, c8 = (idx & 15) * 8;
            CPASYNC16(kd + (r * KHS + c8) * 2, Kh + (size_t)(k0 + r) * CD + hD + c8);
            const int d = idx >> 3, kv8 = (idx & 7) * 8;
            CPASYNC16(td + (d * TTS + kv8) * 2, VTh + (size_t)(hD + d) * KVL + k0 + kv8);
        }
        CPCOMMIT();
    };

    const int NIT = KVL / 64;
    prefetch(0);
    prefetch(1);

    float l0 = 0.f, l1 = 0.f;
    float o[16][4];
#pragma unroll
    for (int ni = 0; ni < 16; ni++)
#pragma unroll
        for (int r = 0; r < 4; r++) o[ni][r] = 0.f;

    for (int it = 0; it < NIT; it++) {
        if (it + 1 < NIT) CPWAIT1(); else CPWAIT0();
        __syncthreads();
        if (it + 2 < NIT) prefetch(it + 2);

        const int s = it % 3;
        const uint32_t Ku = Ktu[s];
        const uint32_t Tu = Ttu[s];

        float sc[8][4];
#pragma unroll
        for (int ni = 0; ni < 8; ni++)
#pragma unroll
            for (int r = 0; r < 4; r++) sc[ni][r] = 0.f;

#pragma unroll
        for (int ks = 0; ks < 8; ks++) {
            const int k = ks * 16;
#pragma unroll
            for (int g = 0; g < 4; g++) {
                uint32_t t[4];
                ldsm4(t, Ku + ((g * 16 + brow) * KHS + k + bcol8) * 2);
                mma_bf16(sc[2 * g],     qf[ks], t);
                mma_bf16(sc[2 * g + 1], qf[ks], t + 2);
            }
        }

#pragma unroll
        for (int ni = 0; ni < 8; ni++) {
            __nv_bfloat162 h01 = __floats2bfloat162_rn(__expf(sc[ni][0]), __expf(sc[ni][1]));
            __nv_bfloat162 h23 = __floats2bfloat162_rn(__expf(sc[ni][2]), __expf(sc[ni][3]));
            l0 += __bfloat162float(h01.x) + __bfloat162float(h01.y);
            l1 += __bfloat162float(h23.x) + __bfloat162float(h23.y);
            Pw[(w16 + gid    ) * (PTS / 2) + ni * 4 + tig] = *(uint32_t*)&h01;
            Pw[(w16 + gid + 8) * (PTS / 2) + ni * 4 + tig] = *(uint32_t*)&h23;
        }
        __syncwarp();

#pragma unroll
        for (int ks = 0; ks < 4; ks++) {
            const int k = ks * 16;
            uint32_t paf[4];
            ldsm4(paf, Psu + ((w16 + arow) * PTS + k + acol8) * 2);
#pragma unroll
            for (int dp = 0; dp < 8; dp++) {
                uint32_t t[4];
                ldsm4(t, Tu + ((dp * 16 + brow) * TTS + k + bcol8) * 2);
                mma_bf16(o[2 * dp],     paf, t);
                mma_bf16(o[2 * dp + 1], paf, t + 2);
            }
        }
    }

    l0 += __shfl_xor_sync(0xffffffffu, l0, 1);
    l0 += __shfl_xor_sync(0xffffffffu, l0, 2);
    l1 += __shfl_xor_sync(0xffffffffu, l1, 1);
    l1 += __shfl_xor_sync(0xffffffffu, l1, 2);

    const float inv0 = 1.f / l0, inv1 = 1.f / l1;
    const int row0 = q0 + w16 + gid;
#pragma unroll
    for (int ni = 0; ni < 16; ni++) {
        const int col = hD + ni * 8 + tig * 2;
        *(float2*)(Og + (size_t)row0 * CD + col) =
            make_float2(o[ni][0] * inv0, o[ni][1] * inv0);
        *(float2*)(Og + (size_t)(row0 + 8) * CD + col) =
            make_float2(o[ni][2] * inv1, o[ni][3] * inv1);
    }
}

// ---------------- position features ----------------
__global__ __launch_bounds__(256) void pos_hidden(
    float* __restrict__ ph, const float* __restrict__ sw1, const float* __restrict__ sb1)
{
    const int idx = blockIdx.x * 256 + threadIdx.x;
    const int l = idx >> 11;
    const int c = idx & 2047;
    const float coord = -1.f + 2.f * (float)l / 2047.f;
    ph[idx] = sinf(30.f * (coord * sw1[c] + sb1[c]));
}

// ---------------- final: out = x + rmsnorm(O + pos, on_w) ----------------
__global__ __launch_bounds__(256) void fuse_out(
    const float* __restrict__ x, const float* __restrict__ ov,
    const float* __restrict__ pos, const float* __restrict__ w,
    float* __restrict__ out)
{
    __shared__ float t[2048];
    __shared__ float red[8];
    const int l = blockIdx.x;
    const int tid = threadIdx.x;
    float sq = 0.f;
    for (int c = tid; c < 2048; c += 256) {
        const float v = ov[(size_t)l * 2048 + c] + pos[(size_t)l * 2048 + c];
        t[c] = v; sq += v * v;
    }
#pragma unroll
    for (int o = 16; o > 0; o >>= 1) sq += __shfl_xor_sync(0xffffffffu, sq, o);
    if ((tid & 31) == 0) red[tid >> 5] = sq;
    __syncthreads();
    float total = 0.f;
#pragma unroll
    for (int i = 0; i < 8; i++) total += red[i];
    const float rn = rsqrtf(total * (1.f / 2048.f) + 1e-6f);
    for (int c = tid; c < 2048; c += 256)
        out[(size_t)l * 2048 + c] = x[(size_t)l * 2048 + c] + t[c] * rn * w[c];
}

// ---------------- launch ----------------
extern "C" void kernel_launch(void* const* d_in, const int* in_sizes, int n_in,
                              void* d_out, int out_size)
{
    (void)in_sizes; (void)n_in; (void)out_size;
    const float* x   = (const float*)d_in[0];
    const float* h0  = (const float*)d_in[1];
    const float* h1  = (const float*)d_in[2];
    const float* h2  = (const float*)d_in[3];
    const float* Wq  = (const float*)d_in[4];
    const float* Wk  = (const float*)d_in[5];
    const float* Wv  = (const float*)d_in[6];
    const float* Wo  = (const float*)d_in[7];
    const float* qn  = (const float*)d_in[8];
    const float* kn  = (const float*)d_in[9];
    const float* on  = (const float*)d_in[10];
    const float* sw1 = (const float*)d_in[11];
    const float* sb1 = (const float*)d_in[12];
    const float* sw2 = (const float*)d_in[13];
    const float* sb2 = (const float*)d_in[14];
    float* out = (float*)d_out;

    float *AO, *O, *PH, *PS;
    __nv_bfloat16 *Qhp, *Khp, *VThp, *BFp;
    cudaGetSymbolAddress((void**)&Qhp,  gQh);
    cudaGetSymbolAddress((void**)&Khp,  gKh);
    cudaGetSymbolAddress((void**)&VThp, gVTh);
    cudaGetSymbolAddress((void**)&BFp,  gBF);
    cudaGetSymbolAddress((void**)&AO,   gAO);
    cudaGetSymbolAddress((void**)&O,    gO);
    cudaGetSymbolAddress((void**)&PH,   gPH);
    cudaGetSymbolAddress((void**)&PS,   gPS);

    cudaFuncSetAttribute(proj5b,       cudaFuncAttributeMaxDynamicSharedMemorySize, BGSMEM);
    cudaFuncSetAttribute(gemm2_kernel, cudaFuncAttributeMaxDynamicSharedMemorySize, GSMEM);
    cudaFuncSetAttribute(flashmma,     cudaFuncAttributeMaxDynamicSharedMemorySize, FSMEM);

    ropetab<<<1, 192>>>();
    pos_hidden<<<(LQ * CD) / 256, 256>>>(PH, sw1, sb1);

    Cvt6 cj;
    cj.s[0] = h0; cj.s[1] = h1; cj.s[2] = h2;
    cj.s[3] = Wq; cj.s[4] = Wk; cj.s[5] = Wv;
    convert6<<<dim3(LQ * CD / 4 / 256, 6), 256>>>(cj, BFp);

    proj5b<<<dim3(16, 16, 5), 128, BGSMEM>>>(BFp, Qhp, Khp, VThp, qn, kn);

    flashmma<<<dim3(16, 16), 256, FSMEM>>>(Qhp, Khp, VThp, AO);

    gemm2_kernel<<<dim3(16, 16, 2), 128, GSMEM>>>(AO, Wo, O, PH, sw2, sb2, PS);

    fuse_out<<<LQ, 256>>>(x, O, PS, on, out);
}

// round 17
// speedup vs baseline: 1.0379x; 1.0379x over previous
#include <cuda_runtime.h>
#include <cuda_bf16.h>
#include <cstdint>
#include <math.h>

#define LQ   2048
#define CD   2048
#define HN   16
#define DD   128
#define KVL  4096
#define LC_  ((size_t)LQ * CD)

// ---------------- scratch (device globals; no allocation) ----------------
__device__ __nv_bfloat16 gQh [LQ  * CD];    // normed+roped+scaled Q, bf16
__device__ __nv_bfloat16 gKh [KVL * CD];    // normed+roped K, bf16
__device__ __nv_bfloat16 gVTh[CD  * KVL];   // V transposed, bf16: [c][kv]
__device__ __nv_bfloat16 gBF [6 * LQ * CD]; // bf16: h0,h1,h2,Wq,Wk,Wv
__device__ float gAO[LQ  * CD];
__device__ float gO [LQ  * CD];
__device__ float gPH[LQ  * CD];
__device__ float gPS[LQ  * CD];
__device__ float gRC[3 * 64];
__device__ float gRS[3 * 64];

// ---------------- helpers ----------------
__device__ __forceinline__ uint32_t packbf(float lo, float hi) {
    __nv_bfloat162 h = __floats2bfloat162_rn(lo, hi);
    return *(uint32_t*)&h;
}
__device__ __forceinline__ void mma_tf32(float c[4], const uint32_t a[4], const uint32_t b[2]) {
    asm volatile(
        "mma.sync.aligned.m16n8k8.row.col.f32.tf32.tf32.f32 "
        "{%0,%1,%2,%3}, {%4,%5,%6,%7}, {%8,%9}, {%0,%1,%2,%3};"
        : "+f"(c[0]), "+f"(c[1]), "+f"(c[2]), "+f"(c[3])
        : "r"(a[0]), "r"(a[1]), "r"(a[2]), "r"(a[3]), "r"(b[0]), "r"(b[1]));
}
__device__ __forceinline__ void mma_bf16(float c[4], const uint32_t a[4], const uint32_t b[2]) {
    asm volatile(
        "mma.sync.aligned.m16n8k16.row.col.f32.bf16.bf16.f32 "
        "{%0,%1,%2,%3}, {%4,%5,%6,%7}, {%8,%9}, {%0,%1,%2,%3};"
        : "+f"(c[0]), "+f"(c[1]), "+f"(c[2]), "+f"(c[3])
        : "r"(a[0]), "r"(a[1]), "r"(a[2]), "r"(a[3]), "r"(b[0]), "r"(b[1]));
}
__device__ __forceinline__ void ldsm4(uint32_t* r, uint32_t addr) {
    asm volatile("ldmatrix.sync.aligned.m8n8.x4.shared.b16 {%0,%1,%2,%3}, [%4];"
        : "=r"(r[0]), "=r"(r[1]), "=r"(r[2]), "=r"(r[3]) : "r"(addr));
}

#define CPASYNC16(dst, src) \
    asm volatile("cp.async.cg.shared.global [%0], [%1], 16;" :: "r"(dst), "l"(src) : "memory")
#define CPCOMMIT()   asm volatile("cp.async.commit_group;" ::: "memory")
#define CPWAIT1()    asm volatile("cp.async.wait_group 1;" ::: "memory")
#define CPWAIT0()    asm volatile("cp.async.wait_group 0;" ::: "memory")

// ---------------- fp32->bf16 conversion (6 tensors) ----------------
struct Cvt6 { const float* s[6]; };
__global__ __launch_bounds__(256) void convert6(Cvt6 js, __nv_bfloat16* dst)
{
    const int z = blockIdx.y;
    const size_t idx = (size_t)blockIdx.x * 256 + threadIdx.x;
    const float4 v = ((const float4*)js.s[z])[idx];
    uint2 u;
    u.x = packbf(v.x, v.y);
    u.y = packbf(v.z, v.w);
    *(uint2*)(dst + z * LC_ + idx * 4) = u;
}

// ---------------- rope tables ----------------
__global__ void ropetab()
{
    const int t = threadIdx.x;
    if (t < 192) {
        const int z = t >> 6, d = t & 63;
        const float depth = (z == 0) ? 2.f : (float)(z - 1);
        const float ang = depth * __expf(-(float)d * 0.14391156f);
        gRC[t] = cosf(ang);
        gRS[t] = sinf(ang);
    }
}

// ---------------- bf16 GEMM mainloop (projections), 2-stage ring ----------------
#define BH_S    72
#define BG_TILE (128 * BH_S * 2)            // 18432 B
#define BGSMEM  (4 * BG_TILE)               // 73728 B -> 3 CTAs/SM
#define EPS_    132                          // epilogue smem stride (mult of 4 for LDS.128)

__device__ __forceinline__ void bgemm_main(
    const __nv_bfloat16* __restrict__ A, const __nv_bfloat16* __restrict__ B,
    float c[4][8][4])
{
    extern __shared__ char smc[];
    const uint32_t sbase = (uint32_t)__cvta_generic_to_shared(smc);

    const int tid  = threadIdx.x;
    const int wid  = tid >> 5, lane = tid & 31;
    const int wm   = (wid & 1) * 64;
    const int wn   = (wid >> 1) * 64;
    const int bm   = blockIdx.y * 128, bn = blockIdx.x * 128;

    const int arow  = lane & 15;
    const int acol8 = (lane >> 4) * 8;
    const int brow  = (lane & 7) + ((lane >> 4) << 3);
    const int bcol8 = ((lane >> 3) & 1) * 8;

    const int NK = CD / 64;   // 32

    auto prefetch = [&](int kc) {
        const int s = kc & 1;
        const int k0 = kc << 6;
        const uint32_t ab = sbase + (2 * s) * BG_TILE;
        const uint32_t bb = sbase + (2 * s + 1) * BG_TILE;
#pragma unroll
        for (int i = 0; i < 8; i++) {
            const int idx = i * 128 + tid;
            const int r = idx >> 3, c8 = (idx & 7) * 8;
            CPASYNC16(ab + (r * BH_S + c8) * 2, A + (size_t)(bm + r) * CD + k0 + c8);
            CPASYNC16(bb + (r * BH_S + c8) * 2, B + (size_t)(bn + r) * CD + k0 + c8);
        }
        CPCOMMIT();
    };

    prefetch(0);

    for (int kc = 0; kc < NK; kc++) {
        const bool more = (kc + 1 < NK);
        if (more) prefetch(kc + 1);
        if (more) CPWAIT1(); else CPWAIT0();
        __syncthreads();

        const int s = kc & 1;
        const uint32_t Au = sbase + (2 * s) * BG_TILE;
        const uint32_t Bu = sbase + (2 * s + 1) * BG_TILE;

#pragma unroll
        for (int ks = 0; ks < 4; ks++) {
            const int k = ks * 16;
            uint32_t af[4][4], bf[8][2];
#pragma unroll
            for (int mi = 0; mi < 4; mi++)
                ldsm4(af[mi], Au + ((wm + mi * 16 + arow) * BH_S + k + acol8) * 2);
#pragma unroll
            for (int p = 0; p < 4; p++) {
                uint32_t t[4];
                ldsm4(t, Bu + ((wn + p * 16 + brow) * BH_S + k + bcol8) * 2);
                bf[2 * p][0] = t[0]; bf[2 * p][1] = t[1];
                bf[2 * p + 1][0] = t[2]; bf[2 * p + 1][1] = t[3];
            }
#pragma unroll
            for (int mi = 0; mi < 4; mi++)
#pragma unroll
                for (int ni = 0; ni < 8; ni++)
                    mma_bf16(c[mi][ni], af[mi], bf[ni]);
        }
        __syncthreads();
    }
}

// fused projections:
//   z=0: h2*Wq  -> rmsnorm(qn)+rope(tbl0)+scale -> Qh bf16
//   z=1: h0*Wk  -> rmsnorm(kn)+rope(tbl1)       -> Kh[0]
//   z=2: h1*Wk  -> rmsnorm(kn)+rope(tbl2)       -> Kh[1]
//   z=3: h0*Wv  -> transpose                    -> VT[:, 0:2048]
//   z=4: h1*Wv  -> transpose                    -> VT[:, 2048:4096]
__global__ __launch_bounds__(128, 3) void proj5b(
    const __nv_bfloat16* __restrict__ BF,
    __nv_bfloat16* __restrict__ Qh, __nv_bfloat16* __restrict__ Kh,
    __nv_bfloat16* __restrict__ VT,
    const float* __restrict__ qn, const float* __restrict__ kn)
{
    const int z = blockIdx.z;
    const __nv_bfloat16 *Ap, *Bp;
    switch (z) {
        case 0:  Ap = BF + 2 * LC_; Bp = BF + 3 * LC_; break;
        case 1:  Ap = BF + 0 * LC_; Bp = BF + 4 * LC_; break;
        case 2:  Ap = BF + 1 * LC_; Bp = BF + 4 * LC_; break;
        case 3:  Ap = BF + 0 * LC_; Bp = BF + 5 * LC_; break;
        default: Ap = BF + 1 * LC_; Bp = BF + 5 * LC_; break;
    }

    float c[4][8][4];
#pragma unroll
    for (int i = 0; i < 4; i++)
#pragma unroll
        for (int j = 0; j < 8; j++)
#pragma unroll
            for (int r = 0; r < 4; r++) c[i][j][r] = 0.f;

    bgemm_main(Ap, Bp, c);

    // ---- stage accumulators to smem fp32 tile [128][EPS_] ----
    extern __shared__ char smc[];
    float* st = (float*)smc;
    const int tid  = threadIdx.x;
    const int wid  = tid >> 5, lane = tid & 31;
    const int gid  = lane >> 2, tig = lane & 3;
    const int wm   = (wid & 1) * 64;
    const int wn   = (wid >> 1) * 64;
    const int bm   = blockIdx.y * 128, bn = blockIdx.x * 128;

#pragma unroll
    for (int mi = 0; mi < 4; mi++) {
        const int r0 = wm + mi * 16 + gid;
#pragma unroll
        for (int ni = 0; ni < 8; ni++) {
            const int col = wn + ni * 8 + tig * 2;
            st[r0 * EPS_ + col]           = c[mi][ni][0];
            st[r0 * EPS_ + col + 1]       = c[mi][ni][1];
            st[(r0 + 8) * EPS_ + col]     = c[mi][ni][2];
            st[(r0 + 8) * EPS_ + col + 1] = c[mi][ni][3];
        }
    }
    __syncthreads();

    if (z <= 2) {
        // ---- rmsnorm + rope per row (warp handles 32 rows) ----
        const float* w = (z == 0) ? qn : kn;
        const float4 wv = *(const float4*)(w + lane * 4);
        const int dd0 = (lane & 15) * 4;
        const float4 cv = *(const float4*)(gRC + z * 64 + dd0);
        const float4 sv = *(const float4*)(gRS + z * 64 + dd0);
        const float qs = (z == 0) ? 0.08838834764831845f : 1.f;
        __nv_bfloat16* dst = (z == 0) ? Qh : (Kh + (size_t)(z - 1) * LC_);

        for (int r8 = 0; r8 < 32; r8++) {
            const int row = wid * 32 + r8;
            float4 v = *(const float4*)&st[row * EPS_ + lane * 4];
            float sq = v.x * v.x + v.y * v.y + v.z * v.z + v.w * v.w;
#pragma unroll
            for (int o = 16; o > 0; o >>= 1) sq += __shfl_xor_sync(0xffffffffu, sq, o);
            const float rn = rsqrtf(sq * (1.f / 128.f) + 1e-6f);

            float4 s = make_float4(v.x * rn * wv.x, v.y * rn * wv.y,
                                   v.z * rn * wv.z, v.w * rn * wv.w);
            float4 q;
            q.x = __shfl_xor_sync(0xffffffffu, s.x, 16);
            q.y = __shfl_xor_sync(0xffffffffu, s.y, 16);
            q.z = __shfl_xor_sync(0xffffffffu, s.z, 16);
            q.w = __shfl_xor_sync(0xffffffffu, s.w, 16);

            float4 out;
            if (lane < 16) {
                out.x = s.x * cv.x - q.x * sv.x;
                out.y = s.y * cv.y - q.y * sv.y;
                out.z = s.z * cv.z - q.z * sv.z;
                out.w = s.w * cv.w - q.w * sv.w;
            } else {
                out.x = q.x * sv.x + s.x * cv.x;
                out.y = q.y * sv.y + s.y * cv.y;
                out.z = q.z * sv.z + s.z * cv.z;
                out.w = q.w * sv.w + s.w * cv.w;
            }
            out.x *= qs; out.y *= qs; out.z *= qs; out.w *= qs;

            uint2 u;
            u.x = packbf(out.x, out.y);
            u.y = packbf(out.z, out.w);
            *(uint2*)(dst + (size_t)(bm + row) * CD + bn + lane * 4) = u;
        }
    } else {
        // ---- transpose to VT[c][kv] bf16 (kv = this CTA's 128 rows) ----
        const int kvb = (z == 3 ? 0 : 2048) + bm;
        for (int j = 0; j < 32; j++) {
            const int ccol = wid + 4 * j;   // 0..127
            const float a0 = st[(lane * 4 + 0) * EPS_ + ccol];
            const float a1 = st[(lane * 4 + 1) * EPS_ + ccol];
            const float a2 = st[(lane * 4 + 2) * EPS_ + ccol];
            const float a3 = st[(lane * 4 + 3) * EPS_ + ccol];
            uint2 u;
            u.x = packbf(a0, a1);
            u.y = packbf(a2, a3);
            *(uint2*)(VT + (size_t)(bn + ccol) * KVL + kvb + lane * 4) = u;
        }
    }
}

// ---------------- tf32 mma.sync GEMM core (Wo + pos), 2-stage ring ----------------
#define GS_TILE 4608
#define GSMEM   (4 * GS_TILE * 4)           // 73728 B -> 3 CTAs/SM

template<bool BT, bool BIAS>
__device__ __forceinline__ void gemm_core(
    const float* __restrict__ A, const float* __restrict__ B,
    const float* __restrict__ bias, float* __restrict__ Cc,
    int M, int N, int K)
{
    extern __shared__ float smemf[];
    const uint32_t sbase = (uint32_t)__cvta_generic_to_shared(smemf);

    const int tid  = threadIdx.x;
    const int wid  = tid >> 5, lane = tid & 31;
    const int gid  = lane >> 2, tig = lane & 3;
    const int wm   = (wid & 1) * 64;
    const int wn   = (wid >> 1) * 64;
    const int bm   = blockIdx.y * 128, bn = blockIdx.x * 128;

    const int arow = lane & 15,                 acol = (lane >> 4) * 4;
    const int brow = (lane & 7) + ((lane >> 4) << 3), bcol = ((lane >> 3) & 1) * 4;

    float c[4][8][4];
#pragma unroll
    for (int i = 0; i < 4; i++)
#pragma unroll
        for (int j = 0; j < 8; j++)
#pragma unroll
            for (int r = 0; r < 4; r++) c[i][j][r] = 0.f;

    const int NK = K >> 5;

    auto prefetch = [&](int kc) {
        const int s = kc & 1;
        const int k0 = kc << 5;
        const uint32_t ab = sbase + ((2 * s) * GS_TILE) * 4;
        const uint32_t bb = sbase + ((2 * s + 1) * GS_TILE) * 4;
#pragma unroll
        for (int i = 0; i < 8; i++) {
            const int idx = i * 128 + tid;
            const int r = idx >> 3, cc = (idx & 7) * 4;
            CPASYNC16(ab + (r * 36 + cc) * 4, A + (size_t)(bm + r) * K + k0 + cc);
        }
        if (BT) {
#pragma unroll
            for (int i = 0; i < 8; i++) {
                const int idx = i * 128 + tid;
                const int r = idx >> 3, cc = (idx & 7) * 4;
                CPASYNC16(bb + (r * 36 + cc) * 4, B + (size_t)(bn + r) * K + k0 + cc);
            }
        } else {
#pragma unroll
            for (int i = 0; i < 8; i++) {
                const int idx = i * 128 + tid;
                const int kr = idx >> 5, cc = (idx & 31) * 4;
                CPASYNC16(bb + (kr * 132 + cc) * 4, B + (size_t)(k0 + kr) * N + bn + cc);
            }
        }
        CPCOMMIT();
    };

    prefetch(0);

    for (int kc = 0; kc < NK; kc++) {
        const bool more = (kc + 1 < NK);
        if (more) prefetch(kc + 1);
        if (more) CPWAIT1(); else CPWAIT0();
        __syncthreads();

        const int s = kc & 1;
        const uint32_t sAu = sbase + ((2 * s) * GS_TILE) * 4;
        const uint32_t sBu = sbase + ((2 * s + 1) * GS_TILE) * 4;
        const float*   sB  = smemf + (2 * s + 1) * GS_TILE;

#pragma unroll
        for (int ks = 0; ks < 4; ks++) {
            const int k = ks * 8;
            uint32_t af[4][4], bf[8][2];
#pragma unroll
            for (int mi = 0; mi < 4; mi++)
                ldsm4(af[mi], sAu + (((wm + mi * 16 + arow) * 36) + k + acol) * 4);
            if (BT) {
#pragma unroll
                for (int p = 0; p < 4; p++) {
                    uint32_t t[4];
                    ldsm4(t, sBu + (((wn + p * 16 + brow) * 36) + k + bcol) * 4);
                    bf[2 * p][0] = t[0]; bf[2 * p][1] = t[1];
                    bf[2 * p + 1][0] = t[2]; bf[2 * p + 1][1] = t[3];
                }
            } else {
#pragma unroll
                for (int ni = 0; ni < 8; ni++) {
                    const int n = wn + ni * 8 + gid;
                    bf[ni][0] = __float_as_uint(sB[(k + tig    ) * 132 + n]);
                    bf[ni][1] = __float_as_uint(sB[(k + tig + 4) * 132 + n]);
                }
            }
#pragma unroll
            for (int mi = 0; mi < 4; mi++)
#pragma unroll
                for (int ni = 0; ni < 8; ni++)
                    mma_tf32(c[mi][ni], af[mi], bf[ni]);
        }
        __syncthreads();
    }

#pragma unroll
    for (int mi = 0; mi < 4; mi++) {
        const int row0 = bm + wm + mi * 16 + gid;
#pragma unroll
        for (int ni = 0; ni < 8; ni++) {
            const int col = bn + wn + ni * 8 + tig * 2;
            float2 v0 = make_float2(c[mi][ni][0], c[mi][ni][1]);
            float2 v1 = make_float2(c[mi][ni][2], c[mi][ni][3]);
            if (BIAS) {
                const float b0 = bias[col], b1 = bias[col + 1];
                v0.x += b0; v0.y += b1; v1.x += b0; v1.y += b1;
            }
            *(float2*)(Cc + (size_t)row0 * N + col)       = v0;
            *(float2*)(Cc + (size_t)(row0 + 8) * N + col) = v1;
        }
    }
}

__global__ __launch_bounds__(128, 3) void gemm2_kernel(
    const float* AO, const float* Wo, float* O,
    const float* PH, const float* sw2, const float* sb2, float* PS)
{
    if (blockIdx.z == 0)
        gemm_core<true,  false>(AO, Wo, nullptr, O, 2048, 2048, 2048);
    else
        gemm_core<false, true >(PH, sw2, sb2, PS, 2048, 2048, 2048);
}

// ---------------- flash attention: bf16 mma.sync + ldmatrix, 3-stage ring ----------------
#define KHS 136
#define TTS 72
#define PTS 72
#define KSTG (64 * KHS)
#define TSTG (128 * TTS)
#define OFF_T (3 * KSTG)
#define OFF_P (OFF_T + 3 * TSTG)
#define FSMEM ((OFF_P + 128 * PTS) * 2)

__global__ __launch_bounds__(256) void flashmma(
    const __nv_bfloat16* __restrict__ Qh, const __nv_bfloat16* __restrict__ Kh,
    const __nv_bfloat16* __restrict__ VTh, float* __restrict__ Og)
{
    extern __shared__ char smc[];
    const uint32_t smu = (uint32_t)__cvta_generic_to_shared(smc);
    const uint32_t Ktu[3] = { smu, smu + KSTG * 2, smu + 2 * KSTG * 2 };
    const uint32_t Ttu[3] = { smu + OFF_T * 2, smu + (OFF_T + TSTG) * 2,
                              smu + (OFF_T + 2 * TSTG) * 2 };
    const uint32_t Psu = smu + OFF_P * 2;
    uint32_t* Pw = (uint32_t*)(smc + OFF_P * 2);

    const int tid  = threadIdx.x;
    const int wid  = tid >> 5, lane = tid & 31;
    const int gid  = lane >> 2, tig = lane & 3;
    const int h    = blockIdx.y;
    const int q0   = blockIdx.x * 128;
    const int hD   = h * DD;
    const int w16  = wid * 16;

    const int arow = lane & 15;
    const int acol8 = (lane >> 4) * 8;
    const int brow = (lane & 7) + ((lane >> 4) << 3);
    const int bcol8 = ((lane >> 3) & 1) * 8;

    // ---- Q fragments: direct bf16 pair loads (scale pre-folded upstream) ----
    uint32_t qf[8][4];
    {
        const __nv_bfloat16* qr0 = Qh + (size_t)(q0 + w16 + gid) * CD + hD;
        const __nv_bfloat16* qr1 = qr0 + (size_t)8 * CD;
#pragma unroll
        for (int ks = 0; ks < 8; ks++) {
            const int k = ks * 16;
            qf[ks][0] = *(const uint32_t*)(qr0 + k + 2 * tig);
            qf[ks][1] = *(const uint32_t*)(qr1 + k + 2 * tig);
            qf[ks][2] = *(const uint32_t*)(qr0 + k + 2 * tig + 8);
            qf[ks][3] = *(const uint32_t*)(qr1 + k + 2 * tig + 8);
        }
    }

    auto prefetch = [&](int it) {
        const int s = it % 3;
        const int k0 = it * 64;
        const uint32_t kd = Ktu[s];
        const uint32_t td = Ttu[s];
#pragma unroll
        for (int i = 0; i < 4; i++) {
            const int idx = i * 256 + tid;
            const int r = idx >> 4, c8 = (idx & 15) * 8;
            CPASYNC16(kd + (r * KHS + c8) * 2, Kh + (size_t)(k0 + r) * CD + hD + c8);
            const int d = idx >> 3, kv8 = (idx & 7) * 8;
            CPASYNC16(td + (d * TTS + kv8) * 2, VTh + (size_t)(hD + d) * KVL + k0 + kv8);
        }
        CPCOMMIT();
    };

    const int NIT = KVL / 64;
    prefetch(0);
    prefetch(1);

    float l0 = 0.f, l1 = 0.f;
    float o[16][4];
#pragma unroll
    for (int ni = 0; ni < 16; ni++)
#pragma unroll
        for (int r = 0; r < 4; r++) o[ni][r] = 0.f;

    for (int it = 0; it < NIT; it++) {
        if (it + 1 < NIT) CPWAIT1(); else CPWAIT0();
        __syncthreads();
        if (it + 2 < NIT) prefetch(it + 2);

        const int s = it % 3;
        const uint32_t Ku = Ktu[s];
        const uint32_t Tu = Ttu[s];

        float sc[8][4];
#pragma unroll
        for (int ni = 0; ni < 8; ni++)
#pragma unroll
            for (int r = 0; r < 4; r++) sc[ni][r] = 0.f;

#pragma unroll
        for (int ks = 0; ks < 8; ks++) {
            const int k = ks * 16;
#pragma unroll
            for (int g = 0; g < 4; g++) {
                uint32_t t[4];
                ldsm4(t, Ku + ((g * 16 + brow) * KHS + k + bcol8) * 2);
                mma_bf16(sc[2 * g],     qf[ks], t);
                mma_bf16(sc[2 * g + 1], qf[ks], t + 2);
            }
        }

#pragma unroll
        for (int ni = 0; ni < 8; ni++) {
            __nv_bfloat162 h01 = __floats2bfloat162_rn(__expf(sc[ni][0]), __expf(sc[ni][1]));
            __nv_bfloat162 h23 = __floats2bfloat162_rn(__expf(sc[ni][2]), __expf(sc[ni][3]));
            l0 += __bfloat162float(h01.x) + __bfloat162float(h01.y);
            l1 += __bfloat162float(h23.x) + __bfloat162float(h23.y);
            Pw[(w16 + gid    ) * (PTS / 2) + ni * 4 + tig] = *(uint32_t*)&h01;
            Pw[(w16 + gid + 8) * (PTS / 2) + ni * 4 + tig] = *(uint32_t*)&h23;
        }
        __syncwarp();

#pragma unroll
        for (int ks = 0; ks < 4; ks++) {
            const int k = ks * 16;
            uint32_t paf[4];
            ldsm4(paf, Psu + ((w16 + arow) * PTS + k + acol8) * 2);
#pragma unroll
            for (int dp = 0; dp < 8; dp++) {
                uint32_t t[4];
                ldsm4(t, Tu + ((dp * 16 + brow) * TTS + k + bcol8) * 2);
                mma_bf16(o[2 * dp],     paf, t);
                mma_bf16(o[2 * dp + 1], paf, t + 2);
            }
        }
    }

    l0 += __shfl_xor_sync(0xffffffffu, l0, 1);
    l0 += __shfl_xor_sync(0xffffffffu, l0, 2);
    l1 += __shfl_xor_sync(0xffffffffu, l1, 1);
    l1 += __shfl_xor_sync(0xffffffffu, l1, 2);

    const float inv0 = 1.f / l0, inv1 = 1.f / l1;
    const int row0 = q0 + w16 + gid;
#pragma unroll
    for (int ni = 0; ni < 16; ni++) {
        const int col = hD + ni * 8 + tig * 2;
        *(float2*)(Og + (size_t)row0 * CD + col) =
            make_float2(o[ni][0] * inv0, o[ni][1] * inv0);
        *(float2*)(Og + (size_t)(row0 + 8) * CD + col) =
            make_float2(o[ni][2] * inv1, o[ni][3] * inv1);
    }
}

// ---------------- position features ----------------
__global__ __launch_bounds__(256) void pos_hidden(
    float* __restrict__ ph, const float* __restrict__ sw1, const float* __restrict__ sb1)
{
    const int idx = blockIdx.x * 256 + threadIdx.x;
    const int l = idx >> 11;
    const int c = idx & 2047;
    const float coord = -1.f + 2.f * (float)l / 2047.f;
    ph[idx] = sinf(30.f * (coord * sw1[c] + sb1[c]));
}

// ---------------- final: out = x + rmsnorm(O + pos, on_w) ----------------
__global__ __launch_bounds__(256) void fuse_out(
    const float* __restrict__ x, const float* __restrict__ ov,
    const float* __restrict__ pos, const float* __restrict__ w,
    float* __restrict__ out)
{
    __shared__ float t[2048];
    __shared__ float red[8];
    const int l = blockIdx.x;
    const int tid = threadIdx.x;
    float sq = 0.f;
    for (int c = tid; c < 2048; c += 256) {
        const float v = ov[(size_t)l * 2048 + c] + pos[(size_t)l * 2048 + c];
        t[c] = v; sq += v * v;
    }
#pragma unroll
    for (int o = 16; o > 0; o >>= 1) sq += __shfl_xor_sync(0xffffffffu, sq, o);
    if ((tid & 31) == 0) red[tid >> 5] = sq;
    __syncthreads();
    float total = 0.f;
#pragma unroll
    for (int i = 0; i < 8; i++) total += red[i];
    const float rn = rsqrtf(total * (1.f / 2048.f) + 1e-6f);
    for (int c = tid; c < 2048; c += 256)
        out[(size_t)l * 2048 + c] = x[(size_t)l * 2048 + c] + t[c] * rn * w[c];
}

// ---------------- launch ----------------
extern "C" void kernel_launch(void* const* d_in, const int* in_sizes, int n_in,
                              void* d_out, int out_size)
{
    (void)in_sizes; (void)n_in; (void)out_size;
    const float* x   = (const float*)d_in[0];
    const float* h0  = (const float*)d_in[1];
    const float* h1  = (const float*)d_in[2];
    const float* h2  = (const float*)d_in[3];
    const float* Wq  = (const float*)d_in[4];
    const float* Wk  = (const float*)d_in[5];
    const float* Wv  = (const float*)d_in[6];
    const float* Wo  = (const float*)d_in[7];
    const float* qn  = (const float*)d_in[8];
    const float* kn  = (const float*)d_in[9];
    const float* on  = (const float*)d_in[10];
    const float* sw1 = (const float*)d_in[11];
    const float* sb1 = (const float*)d_in[12];
    const float* sw2 = (const float*)d_in[13];
    const float* sb2 = (const float*)d_in[14];
    float* out = (float*)d_out;

    float *AO, *O, *PH, *PS;
    __nv_bfloat16 *Qhp, *Khp, *VThp, *BFp;
    cudaGetSymbolAddress((void**)&Qhp,  gQh);
    cudaGetSymbolAddress((void**)&Khp,  gKh);
    cudaGetSymbolAddress((void**)&VThp, gVTh);
    cudaGetSymbolAddress((void**)&BFp,  gBF);
    cudaGetSymbolAddress((void**)&AO,   gAO);
    cudaGetSymbolAddress((void**)&O,    gO);
    cudaGetSymbolAddress((void**)&PH,   gPH);
    cudaGetSymbolAddress((void**)&PS,   gPS);

    cudaFuncSetAttribute(proj5b,       cudaFuncAttributeMaxDynamicSharedMemorySize, BGSMEM);
    cudaFuncSetAttribute(gemm2_kernel, cudaFuncAttributeMaxDynamicSharedMemorySize, GSMEM);
    cudaFuncSetAttribute(flashmma,     cudaFuncAttributeMaxDynamicSharedMemorySize, FSMEM);

    ropetab<<<1, 192>>>();
    pos_hidden<<<(LQ * CD) / 256, 256>>>(PH, sw1, sb1);

    Cvt6 cj;
    cj.s[0] = h0; cj.s[1] = h1; cj.s[2] = h2;
    cj.s[3] = Wq; cj.s[4] = Wk; cj.s[5] = Wv;
    convert6<<<dim3(LQ * CD / 4 / 256, 6), 256>>>(cj, BFp);

    proj5b<<<dim3(16, 16, 5), 128, BGSMEM>>>(BFp, Qhp, Khp, VThp, qn, kn);

    flashmma<<<dim3(16, 16), 256, FSMEM>>>(Qhp, Khp, VThp, AO);

    gemm2_kernel<<<dim3(16, 16, 2), 128, GSMEM>>>(AO, Wo, O, PH, sw2, sb2, PS);

    fuse_out<<<LQ, 256>>>(x, O, PS, on, out);
}